// round 1
// baseline (speedup 1.0000x reference)
#include <cuda_runtime.h>
#include <cstdint>

// ---------------------------------------------------------------------------
// Problem constants (fixed by setup_inputs)
// ---------------------------------------------------------------------------
#define D 128                 // hidden dim
#define N_DST0 25000
#define N_DST1 5000
#define OUTD 64

// ---------------------------------------------------------------------------
// Scratch (static __device__ globals; no allocations anywhere)
// ---------------------------------------------------------------------------
__device__ float4 g_z0[100000 * 32];      // z after input GEMM (layer-1 src feats)
__device__ float4 g_wz[100000 * 32];      // W*z (reused for layer 2)
__device__ float4 g_z1[25000 * 32];       // layer-1 output
__device__ float4 g_z2[5000 * 32];        // layer-2 output
__device__ float4 g_acc_one[25000 * 32];  // segment sums
__device__ float4 g_acc_eh[25000 * 32];
__device__ float4 g_acc_ih[25000 * 32];
__device__ float  g_deg[25000];
__device__ float2 g_pe_src[100000];
__device__ float2 g_pe_dst[25000];
__device__ float  g_pi_src[100000];
__device__ float  g_pi_dst[25000];
__device__ float2 g_nalpha[25000];

// ---------------------------------------------------------------------------
// Vector float atomics (sm_90+): 4 f32 adds in one L2 reduction op
// ---------------------------------------------------------------------------
__device__ __forceinline__ void red4(float* addr, float a, float b, float c, float d)
{
    asm volatile("red.global.add.v4.f32 [%0], {%1,%2,%3,%4};"
                 :: "l"(addr), "f"(a), "f"(b), "f"(c), "f"(d) : "memory");
}

// ---------------------------------------------------------------------------
// SGEMM:  C[M,BN] = A[M,K] @ B[K,BN] + bias[BN]
// BM=64, BK=16, 256 threads, per-thread 4 x (BN/16) micro-tile
// ---------------------------------------------------------------------------
template <int BN>
__global__ void gemm_bias_kernel(const float* __restrict__ A,
                                 const float* __restrict__ B,
                                 const float* __restrict__ bias,
                                 float* __restrict__ C,
                                 int M, int K)
{
    constexpr int BM = 64, BK = 16;
    constexpr int TN = BN / 16;           // 8 (BN=128) or 4 (BN=64)
    __shared__ float As[BK][BM];
    __shared__ float Bs[BK][BN];

    const int tid = threadIdx.x;
    const int m0  = blockIdx.x * BM;
    const int tx  = tid & 15;
    const int ty  = tid >> 4;
    const int r0  = ty * 4;
    const int c0  = tx * TN;

    float acc[4][TN];
#pragma unroll
    for (int i = 0; i < 4; ++i)
#pragma unroll
        for (int j = 0; j < TN; ++j) acc[i][j] = 0.f;

    float bb[TN];
#pragma unroll
    for (int j = 0; j < TN; ++j) bb[j] = bias[c0 + j];

    for (int k0 = 0; k0 < K; k0 += BK) {
        // A tile: 64x16 floats, 1 float4 per thread, transpose into As[k][row]
        {
            const int row = tid >> 2;
            const int kk  = (tid & 3) * 4;
            float4 a = make_float4(0.f, 0.f, 0.f, 0.f);
            if (m0 + row < M)
                a = *reinterpret_cast<const float4*>(A + (size_t)(m0 + row) * K + k0 + kk);
            As[kk + 0][row] = a.x;
            As[kk + 1][row] = a.y;
            As[kk + 2][row] = a.z;
            As[kk + 3][row] = a.w;
        }
        // B tile: BKxBN floats
#pragma unroll
        for (int i = tid; i < BK * BN / 4; i += 256) {
            const int kk = i / (BN / 4);
            const int cc = (i % (BN / 4)) * 4;
            *reinterpret_cast<float4*>(&Bs[kk][cc]) =
                *reinterpret_cast<const float4*>(B + (size_t)(k0 + kk) * BN + cc);
        }
        __syncthreads();

#pragma unroll
        for (int k = 0; k < BK; ++k) {
            float a[4];
            *reinterpret_cast<float4*>(a) = *reinterpret_cast<const float4*>(&As[k][r0]);
            float b[TN];
#pragma unroll
            for (int j = 0; j < TN; j += 4)
                *reinterpret_cast<float4*>(&b[j]) =
                    *reinterpret_cast<const float4*>(&Bs[k][c0 + j]);
#pragma unroll
            for (int i = 0; i < 4; ++i)
#pragma unroll
                for (int j = 0; j < TN; ++j) acc[i][j] += a[i] * b[j];
        }
        __syncthreads();
    }

#pragma unroll
    for (int i = 0; i < 4; ++i) {
        const int row = m0 + r0 + i;
        if (row < M) {
#pragma unroll
            for (int j = 0; j < TN; j += 4) {
                float4 v;
                v.x = acc[i][j + 0] + bb[j + 0];
                v.y = acc[i][j + 1] + bb[j + 1];
                v.z = acc[i][j + 2] + bb[j + 2];
                v.w = acc[i][j + 3] + bb[j + 3];
                *reinterpret_cast<float4*>(C + (size_t)row * BN + c0 + j) = v;
            }
        }
    }
}

// ---------------------------------------------------------------------------
// Per-node attention projections: one warp per node.
// pe_src = z_i @ ea[0:128,:]   (2)    pe_dst = z_i @ ea[128:256,:] (2, i<n_dst)
// pi_src = z_i @ ia[0:128]     (1)    pi_dst = z_i @ ia[128:256]   (1, i<n_dst)
// nalpha = softmax(z_i @ na)   (2, i<n_dst)
// ---------------------------------------------------------------------------
__global__ void proj_kernel(const float4* __restrict__ z, int n_src, int n_dst,
                            const float* __restrict__ na,   // [128,2]
                            const float* __restrict__ ea,   // [256,2]
                            const float* __restrict__ ia,   // [256,1]
                            float2* __restrict__ pe_src, float2* __restrict__ pe_dst,
                            float* __restrict__ pi_src, float* __restrict__ pi_dst,
                            float2* __restrict__ nalpha)
{
    const int warp = (blockIdx.x * blockDim.x + threadIdx.x) >> 5;
    const int lane = threadIdx.x & 31;
    if (warp >= n_src) return;

    const float4 z4 = z[(size_t)warp * 32 + lane];

    const float4* ea4 = reinterpret_cast<const float4*>(ea);  // [(256*2)/4]
    const float4 e0 = ea4[lane * 2 + 0];   // rows 4*lane,4*lane+1 (c0,c1 interleaved)
    const float4 e1 = ea4[lane * 2 + 1];   // rows 4*lane+2,4*lane+3
    float pes0 = z4.x * e0.x + z4.y * e0.z + z4.z * e1.x + z4.w * e1.z;
    float pes1 = z4.x * e0.y + z4.y * e0.w + z4.z * e1.y + z4.w * e1.w;

    const float4 d0 = ea4[64 + lane * 2 + 0];
    const float4 d1 = ea4[64 + lane * 2 + 1];
    float ped0 = z4.x * d0.x + z4.y * d0.z + z4.z * d1.x + z4.w * d1.z;
    float ped1 = z4.x * d0.y + z4.y * d0.w + z4.z * d1.y + z4.w * d1.w;

    const float4 i0 = *reinterpret_cast<const float4*>(ia + lane * 4);
    float pis = z4.x * i0.x + z4.y * i0.y + z4.z * i0.z + z4.w * i0.w;
    const float4 i1 = *reinterpret_cast<const float4*>(ia + 128 + lane * 4);
    float pid = z4.x * i1.x + z4.y * i1.y + z4.z * i1.z + z4.w * i1.w;

    const float4* na4 = reinterpret_cast<const float4*>(na);
    const float4 n0 = na4[lane * 2 + 0];
    const float4 n1 = na4[lane * 2 + 1];
    float nl0 = z4.x * n0.x + z4.y * n0.z + z4.z * n1.x + z4.w * n1.z;
    float nl1 = z4.x * n0.y + z4.y * n0.w + z4.z * n1.y + z4.w * n1.w;

#pragma unroll
    for (int off = 16; off; off >>= 1) {
        pes0 += __shfl_xor_sync(0xffffffffu, pes0, off);
        pes1 += __shfl_xor_sync(0xffffffffu, pes1, off);
        ped0 += __shfl_xor_sync(0xffffffffu, ped0, off);
        ped1 += __shfl_xor_sync(0xffffffffu, ped1, off);
        pis  += __shfl_xor_sync(0xffffffffu, pis, off);
        pid  += __shfl_xor_sync(0xffffffffu, pid, off);
        nl0  += __shfl_xor_sync(0xffffffffu, nl0, off);
        nl1  += __shfl_xor_sync(0xffffffffu, nl1, off);
    }

    if (lane == 0) {
        pe_src[warp] = make_float2(pes0, pes1);
        pi_src[warp] = pis;
        if (warp < n_dst) {
            pe_dst[warp] = make_float2(ped0, ped1);
            pi_dst[warp] = pid;
            const float mx = fmaxf(nl0, nl1);
            const float a  = __expf(nl0 - mx);
            const float b  = __expf(nl1 - mx);
            const float inv = 1.f / (a + b);
            nalpha[warp] = make_float2(a * inv, b * inv);
        }
    }
}

// ---------------------------------------------------------------------------
// Zero the three accumulators + degree
// ---------------------------------------------------------------------------
__global__ void zero_kernel(float4* a, float4* b, float4* c, float* deg, int n_dst)
{
    const int i = blockIdx.x * blockDim.x + threadIdx.x;
    const int n4 = n_dst * 32;
    if (i < n4) {
        const float4 z = make_float4(0.f, 0.f, 0.f, 0.f);
        a[i] = z; b[i] = z; c[i] = z;
    }
    if (i < n_dst) deg[i] = 0.f;
}

// ---------------------------------------------------------------------------
// E-channel edge kernel: 2-way softmax attn, scatter a0*wz[s] and a1*z[s]
// One warp per edge (128 floats -> 1 float4 per lane).
// ---------------------------------------------------------------------------
__global__ void edge_e_kernel(const int* __restrict__ es, const int* __restrict__ ed, int E,
                              const float2* __restrict__ pe_src, const float2* __restrict__ pe_dst,
                              const float4* __restrict__ wz, const float4* __restrict__ z,
                              float4* __restrict__ acc_one, float4* __restrict__ acc_eh,
                              float* __restrict__ deg)
{
    const int warp = (blockIdx.x * blockDim.x + threadIdx.x) >> 5;
    const int lane = threadIdx.x & 31;
    if (warp >= E) return;
    const int s = es[warp];
    const int d = ed[warp];
    const float2 ps = pe_src[s];
    const float2 pd = pe_dst[d];
    const float l0 = ps.x + pd.x, l1 = ps.y + pd.y;
    const float mx = fmaxf(l0, l1);
    const float e0 = __expf(l0 - mx), e1 = __expf(l1 - mx);
    const float inv = 1.f / (e0 + e1);
    const float a0 = e0 * inv, a1 = e1 * inv;

    const float4 w  = wz[(size_t)s * 32 + lane];
    const float4 zz = z [(size_t)s * 32 + lane];
    red4(reinterpret_cast<float*>(acc_one + (size_t)d * 32 + lane),
         a0 * w.x, a0 * w.y, a0 * w.z, a0 * w.w);
    red4(reinterpret_cast<float*>(acc_eh + (size_t)d * 32 + lane),
         a1 * zz.x, a1 * zz.y, a1 * zz.z, a1 * zz.w);
    if (lane == 0) atomicAdd(deg + d, 1.f);
}

// ---------------------------------------------------------------------------
// I-channel edge kernel: sigmoid attn, scatter g*z[s]
// ---------------------------------------------------------------------------
__global__ void edge_i_kernel(const int* __restrict__ es, const int* __restrict__ ed, int E,
                              const float* __restrict__ pi_src, const float* __restrict__ pi_dst,
                              const float4* __restrict__ z, float4* __restrict__ acc_ih)
{
    const int warp = (blockIdx.x * blockDim.x + threadIdx.x) >> 5;
    const int lane = threadIdx.x & 31;
    if (warp >= E) return;
    const int s = es[warp];
    const int d = ed[warp];
    const float x = pi_src[s] + pi_dst[d];
    const float g = 1.f / (1.f + __expf(-x));
    const float4 zz = z[(size_t)s * 32 + lane];
    red4(reinterpret_cast<float*>(acc_ih + (size_t)d * 32 + lane),
         g * zz.x, g * zz.y, g * zz.z, g * zz.w);
}

// ---------------------------------------------------------------------------
// Combine: z_out = 0.5*( relu(acc_one/max(deg,1)) + a0*z + relu(acc_eh*acc_ih) + a1*z )
// ---------------------------------------------------------------------------
__global__ void combine_kernel(const float4* __restrict__ acc_one,
                               const float4* __restrict__ acc_eh,
                               const float4* __restrict__ acc_ih,
                               const float* __restrict__ deg,
                               const float2* __restrict__ nalpha,
                               const float4* __restrict__ z,
                               float4* __restrict__ zout, int n_dst)
{
    const int i = blockIdx.x * blockDim.x + threadIdx.x;
    if (i >= n_dst * 32) return;
    const int node = i >> 5;
    const float invd = 1.f / fmaxf(deg[node], 1.f);
    const float2 na = nalpha[node];
    const float nz = na.x + na.y;
    const float4 o  = acc_one[i];
    const float4 eh = acc_eh[i];
    const float4 ih = acc_ih[i];
    const float4 zz = z[i];
    float4 r;
    r.x = 0.5f * (fmaxf(o.x * invd, 0.f) + fmaxf(eh.x * ih.x, 0.f) + nz * zz.x);
    r.y = 0.5f * (fmaxf(o.y * invd, 0.f) + fmaxf(eh.y * ih.y, 0.f) + nz * zz.y);
    r.z = 0.5f * (fmaxf(o.z * invd, 0.f) + fmaxf(eh.z * ih.z, 0.f) + nz * zz.z);
    r.w = 0.5f * (fmaxf(o.w * invd, 0.f) + fmaxf(eh.w * ih.w, 0.f) + nz * zz.w);
    zout[i] = r;
}

// ---------------------------------------------------------------------------
// Host launcher
// ---------------------------------------------------------------------------
static void run_layer(const float4* z, const float4* wz,
                      int n_src, int n_dst,
                      const float* na, const float* ea, const float* ia,
                      const int* es, const int* ed, int Ee,
                      const int* is_, const int* id_, int Ei,
                      float4* pz0, float4* pwz_unused, float4* zout,
                      float4* acc_one, float4* acc_eh, float4* acc_ih,
                      float* deg, float2* pe_src, float2* pe_dst,
                      float* pi_src, float* pi_dst, float2* nalpha)
{
    (void)pz0; (void)pwz_unused;
    {
        const int threads = 256;
        const int blocks = (n_src * 32 + threads - 1) / threads;
        proj_kernel<<<blocks, threads>>>(z, n_src, n_dst, na, ea, ia,
                                         pe_src, pe_dst, pi_src, pi_dst, nalpha);
    }
    {
        const int threads = 256;
        const int blocks = (n_dst * 32 + threads - 1) / threads;
        zero_kernel<<<blocks, threads>>>(acc_one, acc_eh, acc_ih, deg, n_dst);
    }
    {
        const int threads = 256;
        const int blocks = (Ee + 7) / 8;
        edge_e_kernel<<<blocks, threads>>>(es, ed, Ee, pe_src, pe_dst, wz, z,
                                           acc_one, acc_eh, deg);
    }
    {
        const int threads = 256;
        const int blocks = (Ei + 7) / 8;
        edge_i_kernel<<<blocks, threads>>>(is_, id_, Ei, pi_src, pi_dst, z, acc_ih);
    }
    {
        const int threads = 256;
        const int blocks = (n_dst * 32 + threads - 1) / threads;
        combine_kernel<<<blocks, threads>>>(acc_one, acc_eh, acc_ih, deg, nalpha,
                                            z, zout, n_dst);
    }
}

extern "C" void kernel_launch(void* const* d_in, const int* in_sizes, int n_in,
                              void* d_out, int out_size)
{
    const float* feat = (const float*)d_in[0];
    const int* src0[2] = {(const int*)d_in[1], (const int*)d_in[3]};  // cor, sim
    const int* dst0[2] = {(const int*)d_in[2], (const int*)d_in[4]};
    const int* src1[2] = {(const int*)d_in[5], (const int*)d_in[7]};
    const int* dst1[2] = {(const int*)d_in[6], (const int*)d_in[8]};
    const int E0 = in_sizes[1];
    const int E1 = in_sizes[5];

    const int b = n_in - 14;  // robust to scalar inputs being present or not
    const float* Win  = (const float*)d_in[b + 0];
    const float* b_in = (const float*)d_in[b + 1];
    const float* na1  = (const float*)d_in[b + 2];
    const float* ea1  = (const float*)d_in[b + 3];
    const float* ia1  = (const float*)d_in[b + 4];
    const float* W1   = (const float*)d_in[b + 5];
    const float* b1   = (const float*)d_in[b + 6];
    const float* na2  = (const float*)d_in[b + 7];
    const float* ea2  = (const float*)d_in[b + 8];
    const float* ia2  = (const float*)d_in[b + 9];
    const float* W2   = (const float*)d_in[b + 10];
    const float* b2   = (const float*)d_in[b + 11];
    const float* Wout = (const float*)d_in[b + 12];
    const float* bout = (const float*)d_in[b + 13];

    const int F = in_sizes[b + 0] / (2 * D);  // 256
    const int n_src0 = in_sizes[0] / F;       // 100000
    const int n_dst0 = N_DST0;
    const int n_dst1 = N_DST1;
    const int n_src1 = n_dst0;

    // Resolve scratch symbol addresses
    float4 *z0, *wz, *z1, *z2, *acc_one, *acc_eh, *acc_ih;
    float *deg, *pi_src, *pi_dst;
    float2 *pe_src, *pe_dst, *nalpha;
    cudaGetSymbolAddress((void**)&z0, g_z0);
    cudaGetSymbolAddress((void**)&wz, g_wz);
    cudaGetSymbolAddress((void**)&z1, g_z1);
    cudaGetSymbolAddress((void**)&z2, g_z2);
    cudaGetSymbolAddress((void**)&acc_one, g_acc_one);
    cudaGetSymbolAddress((void**)&acc_eh, g_acc_eh);
    cudaGetSymbolAddress((void**)&acc_ih, g_acc_ih);
    cudaGetSymbolAddress((void**)&deg, g_deg);
    cudaGetSymbolAddress((void**)&pe_src, g_pe_src);
    cudaGetSymbolAddress((void**)&pe_dst, g_pe_dst);
    cudaGetSymbolAddress((void**)&pi_src, g_pi_src);
    cudaGetSymbolAddress((void**)&pi_dst, g_pi_dst);
    cudaGetSymbolAddress((void**)&nalpha, g_nalpha);

    float* out = (float*)d_out;

    for (int m = 0; m < 2; ++m) {
        // z0 = feat @ Win[m] + b_in[m]
        gemm_bias_kernel<128><<<(n_src0 + 63) / 64, 256>>>(
            feat, Win + (size_t)m * F * D, b_in + (size_t)m * D,
            (float*)z0, n_src0, F);

        // wz = z0 @ W1[m] + b1[m]
        gemm_bias_kernel<128><<<(n_src0 + 63) / 64, 256>>>(
            (const float*)z0, W1 + (size_t)m * D * D, b1 + (size_t)m * D,
            (float*)wz, n_src0, D);

        // Layer 1 (graph 0): e-channel = mode edge list, i-channel = other one
        run_layer(z0, wz, n_src0, n_dst0,
                  na1 + (size_t)m * D * 2, ea1 + (size_t)m * 2 * D * 2,
                  ia1 + (size_t)m * 2 * D,
                  src0[m], dst0[m], E0, src0[1 - m], dst0[1 - m], E0,
                  nullptr, nullptr, z1,
                  acc_one, acc_eh, acc_ih, deg, pe_src, pe_dst, pi_src, pi_dst, nalpha);

        // wz = z1 @ W2[m] + b2[m]
        gemm_bias_kernel<128><<<(n_src1 + 63) / 64, 256>>>(
            (const float*)z1, W2 + (size_t)m * D * D, b2 + (size_t)m * D,
            (float*)wz, n_src1, D);

        // Layer 2 (graph 1)
        run_layer(z1, wz, n_src1, n_dst1,
                  na2 + (size_t)m * D * 2, ea2 + (size_t)m * 2 * D * 2,
                  ia2 + (size_t)m * 2 * D,
                  src1[m], dst1[m], E1, src1[1 - m], dst1[1 - m], E1,
                  nullptr, nullptr, z2,
                  acc_one, acc_eh, acc_ih, deg, pe_src, pe_dst, pi_src, pi_dst, nalpha);

        // out[m] = z2 @ Wout[m] + bout[m]
        gemm_bias_kernel<64><<<(n_dst1 + 63) / 64, 256>>>(
            (const float*)z2, Wout + (size_t)m * D * OUTD, bout + (size_t)m * OUTD,
            out + (size_t)m * n_dst1 * OUTD, n_dst1, D);
    }
    (void)out_size;
}

// round 2
// speedup vs baseline: 1.4325x; 1.4325x over previous
#include <cuda_runtime.h>
#include <mma.h>
#include <cstdint>

using namespace nvcuda;

// ---------------------------------------------------------------------------
// Problem constants (fixed by setup_inputs)
// ---------------------------------------------------------------------------
#define D 128                 // hidden dim
#define N_DST0 25000
#define N_DST1 5000
#define OUTD 64

// ---------------------------------------------------------------------------
// Scratch (static __device__ globals; no allocations anywhere)
// ---------------------------------------------------------------------------
__device__ float4 g_z0[100000 * 32];      // z after input GEMM (layer-1 src feats)
__device__ float4 g_wz[100000 * 32];      // W*z (reused for layer 2)
__device__ float4 g_z1[25000 * 32];       // layer-1 output
__device__ float4 g_z2[5000 * 32];        // layer-2 output
__device__ float4 g_acc_one[25000 * 32];  // segment sums
__device__ float4 g_acc_eh[25000 * 32];
__device__ float4 g_acc_ih[25000 * 32];
__device__ float  g_deg[25000];
__device__ float2 g_pe_src[100000];
__device__ float2 g_pe_dst[25000];
__device__ float  g_pi_src[100000];
__device__ float  g_pi_dst[25000];
__device__ float2 g_nalpha[25000];

// ---------------------------------------------------------------------------
// Vector float atomics (sm_90+): 4 f32 adds in one L2 reduction op
// ---------------------------------------------------------------------------
__device__ __forceinline__ void red4(float* addr, float a, float b, float c, float d)
{
    asm volatile("red.global.add.v4.f32 [%0], {%1,%2,%3,%4};"
                 :: "l"(addr), "f"(a), "f"(b), "f"(c), "f"(d) : "memory");
}

// ---------------------------------------------------------------------------
// TF32 tensor-core GEMM:  C[M,BN] = A[M,K] @ B[K,BN] + bias[BN]
// BM=64, BK=16, 256 threads (8 warps in 2x4), warp tile 32 x (BN/4),
// wmma m16n16k8 tf32 fragments, fp32 accumulate.
// ---------------------------------------------------------------------------
template <int BN>
__global__ void gemm_tf32_kernel(const float* __restrict__ A,
                                 const float* __restrict__ B,
                                 const float* __restrict__ bias,
                                 float* __restrict__ C,
                                 int M, int K)
{
    constexpr int BM  = 64, BK = 16;
    constexpr int BNP = BN + 8;            // padded ld for smem B / C staging
    constexpr int WN  = BN / 4;            // 32 (BN=128) or 16 (BN=64)
    constexpr int FN  = WN / 16;           // 2 or 1
    constexpr int FM  = 2;                 // warp covers 32 rows

    __shared__ float sbuf[BM * BNP];       // holds As+Bs during loop, Cs after
    float* As = sbuf;                      // [BM][BK]
    float* Bs = sbuf + BM * BK;            // [BK][BNP]

    const int tid    = threadIdx.x;
    const int warp   = tid >> 5;
    const int warp_m = warp & 1;           // 0..1
    const int warp_n = warp >> 1;          // 0..3
    const int m0     = blockIdx.x * BM;

    wmma::fragment<wmma::accumulator, 16, 16, 8, float> acc[FM][FN];
#pragma unroll
    for (int i = 0; i < FM; ++i)
#pragma unroll
        for (int j = 0; j < FN; ++j) wmma::fill_fragment(acc[i][j], 0.f);

    for (int k0 = 0; k0 < K; k0 += BK) {
        // ---- load A tile 64x16 (1 float4/thread) ----
        {
            const int row = tid >> 2;
            const int cc  = (tid & 3) * 4;
            float4 a = make_float4(0.f, 0.f, 0.f, 0.f);
            if (m0 + row < M)
                a = *reinterpret_cast<const float4*>(A + (size_t)(m0 + row) * K + k0 + cc);
            *reinterpret_cast<float4*>(As + row * BK + cc) = a;
        }
        // ---- load B tile 16xBN ----
#pragma unroll
        for (int i = tid; i < BK * BN / 4; i += 256) {
            const int row = i / (BN / 4);
            const int cc  = (i % (BN / 4)) * 4;
            *reinterpret_cast<float4*>(Bs + row * BNP + cc) =
                *reinterpret_cast<const float4*>(B + (size_t)(k0 + row) * BN + cc);
        }
        __syncthreads();

#pragma unroll
        for (int ks = 0; ks < 2; ++ks) {
            wmma::fragment<wmma::matrix_a, 16, 16, 8, wmma::precision::tf32, wmma::row_major> af[FM];
            wmma::fragment<wmma::matrix_b, 16, 16, 8, wmma::precision::tf32, wmma::row_major> bf[FN];
#pragma unroll
            for (int i = 0; i < FM; ++i) {
                wmma::load_matrix_sync(af[i], As + (warp_m * 32 + i * 16) * BK + ks * 8, BK);
#pragma unroll
                for (int e = 0; e < af[i].num_elements; ++e)
                    af[i].x[e] = wmma::__float_to_tf32(af[i].x[e]);
            }
#pragma unroll
            for (int j = 0; j < FN; ++j) {
                wmma::load_matrix_sync(bf[j], Bs + (ks * 8) * BNP + warp_n * WN + j * 16, BNP);
#pragma unroll
                for (int e = 0; e < bf[j].num_elements; ++e)
                    bf[j].x[e] = wmma::__float_to_tf32(bf[j].x[e]);
            }
#pragma unroll
            for (int i = 0; i < FM; ++i)
#pragma unroll
                for (int j = 0; j < FN; ++j)
                    wmma::mma_sync(acc[i][j], af[i], bf[j], acc[i][j]);
        }
        __syncthreads();
    }

    // ---- stage accumulators to smem, then guarded vectorized writeout + bias ----
    float* Cs = sbuf;
#pragma unroll
    for (int i = 0; i < FM; ++i)
#pragma unroll
        for (int j = 0; j < FN; ++j)
            wmma::store_matrix_sync(Cs + (warp_m * 32 + i * 16) * BNP + warp_n * WN + j * 16,
                                    acc[i][j], BNP, wmma::mem_row_major);
    __syncthreads();

#pragma unroll
    for (int i = tid; i < BM * BN / 4; i += 256) {
        const int row = i / (BN / 4);
        const int cc  = (i % (BN / 4)) * 4;
        if (m0 + row < M) {
            float4 v = *reinterpret_cast<const float4*>(Cs + row * BNP + cc);
            const float4 bb = *reinterpret_cast<const float4*>(bias + cc);
            v.x += bb.x; v.y += bb.y; v.z += bb.z; v.w += bb.w;
            *reinterpret_cast<float4*>(C + (size_t)(m0 + row) * BN + cc) = v;
        }
    }
}

// ---------------------------------------------------------------------------
// Per-node attention projections: one warp per node.
// ---------------------------------------------------------------------------
__global__ void proj_kernel(const float4* __restrict__ z, int n_src, int n_dst,
                            const float* __restrict__ na,   // [128,2]
                            const float* __restrict__ ea,   // [256,2]
                            const float* __restrict__ ia,   // [256,1]
                            float2* __restrict__ pe_src, float2* __restrict__ pe_dst,
                            float* __restrict__ pi_src, float* __restrict__ pi_dst,
                            float2* __restrict__ nalpha)
{
    const int warp = (blockIdx.x * blockDim.x + threadIdx.x) >> 5;
    const int lane = threadIdx.x & 31;
    if (warp >= n_src) return;

    const float4 z4 = z[(size_t)warp * 32 + lane];

    const float4* ea4 = reinterpret_cast<const float4*>(ea);
    const float4 e0 = ea4[lane * 2 + 0];
    const float4 e1 = ea4[lane * 2 + 1];
    float pes0 = z4.x * e0.x + z4.y * e0.z + z4.z * e1.x + z4.w * e1.z;
    float pes1 = z4.x * e0.y + z4.y * e0.w + z4.z * e1.y + z4.w * e1.w;

    const float4 d0 = ea4[64 + lane * 2 + 0];
    const float4 d1 = ea4[64 + lane * 2 + 1];
    float ped0 = z4.x * d0.x + z4.y * d0.z + z4.z * d1.x + z4.w * d1.z;
    float ped1 = z4.x * d0.y + z4.y * d0.w + z4.z * d1.y + z4.w * d1.w;

    const float4 i0 = *reinterpret_cast<const float4*>(ia + lane * 4);
    float pis = z4.x * i0.x + z4.y * i0.y + z4.z * i0.z + z4.w * i0.w;
    const float4 i1 = *reinterpret_cast<const float4*>(ia + 128 + lane * 4);
    float pid = z4.x * i1.x + z4.y * i1.y + z4.z * i1.z + z4.w * i1.w;

    const float4* na4 = reinterpret_cast<const float4*>(na);
    const float4 n0 = na4[lane * 2 + 0];
    const float4 n1 = na4[lane * 2 + 1];
    float nl0 = z4.x * n0.x + z4.y * n0.z + z4.z * n1.x + z4.w * n1.z;
    float nl1 = z4.x * n0.y + z4.y * n0.w + z4.z * n1.y + z4.w * n1.w;

#pragma unroll
    for (int off = 16; off; off >>= 1) {
        pes0 += __shfl_xor_sync(0xffffffffu, pes0, off);
        pes1 += __shfl_xor_sync(0xffffffffu, pes1, off);
        ped0 += __shfl_xor_sync(0xffffffffu, ped0, off);
        ped1 += __shfl_xor_sync(0xffffffffu, ped1, off);
        pis  += __shfl_xor_sync(0xffffffffu, pis, off);
        pid  += __shfl_xor_sync(0xffffffffu, pid, off);
        nl0  += __shfl_xor_sync(0xffffffffu, nl0, off);
        nl1  += __shfl_xor_sync(0xffffffffu, nl1, off);
    }

    if (lane == 0) {
        pe_src[warp] = make_float2(pes0, pes1);
        pi_src[warp] = pis;
        if (warp < n_dst) {
            pe_dst[warp] = make_float2(ped0, ped1);
            pi_dst[warp] = pid;
            const float mx = fmaxf(nl0, nl1);
            const float a  = __expf(nl0 - mx);
            const float b  = __expf(nl1 - mx);
            const float inv = 1.f / (a + b);
            nalpha[warp] = make_float2(a * inv, b * inv);
        }
    }
}

// ---------------------------------------------------------------------------
// E-channel edge kernel: 2-way softmax attn, scatter a0*wz[s] and a1*z[s]
// ---------------------------------------------------------------------------
__global__ void edge_e_kernel(const int* __restrict__ es, const int* __restrict__ ed, int E,
                              const float2* __restrict__ pe_src, const float2* __restrict__ pe_dst,
                              const float4* __restrict__ wz, const float4* __restrict__ z,
                              float4* __restrict__ acc_one, float4* __restrict__ acc_eh,
                              float* __restrict__ deg)
{
    const int warp = (blockIdx.x * blockDim.x + threadIdx.x) >> 5;
    const int lane = threadIdx.x & 31;
    if (warp >= E) return;
    const int s = __ldg(es + warp);
    const int d = __ldg(ed + warp);
    const float2 ps = pe_src[s];
    const float2 pd = pe_dst[d];
    const float l0 = ps.x + pd.x, l1 = ps.y + pd.y;
    const float mx = fmaxf(l0, l1);
    const float e0 = __expf(l0 - mx), e1 = __expf(l1 - mx);
    const float inv = 1.f / (e0 + e1);
    const float a0 = e0 * inv, a1 = e1 * inv;

    const float4 w  = wz[(size_t)s * 32 + lane];
    const float4 zz = z [(size_t)s * 32 + lane];
    red4(reinterpret_cast<float*>(acc_one + (size_t)d * 32 + lane),
         a0 * w.x, a0 * w.y, a0 * w.z, a0 * w.w);
    red4(reinterpret_cast<float*>(acc_eh + (size_t)d * 32 + lane),
         a1 * zz.x, a1 * zz.y, a1 * zz.z, a1 * zz.w);
    if (lane == 0) atomicAdd(deg + d, 1.f);
}

// ---------------------------------------------------------------------------
// I-channel edge kernel: sigmoid attn, scatter g*z[s]
// ---------------------------------------------------------------------------
__global__ void edge_i_kernel(const int* __restrict__ es, const int* __restrict__ ed, int E,
                              const float* __restrict__ pi_src, const float* __restrict__ pi_dst,
                              const float4* __restrict__ z, float4* __restrict__ acc_ih)
{
    const int warp = (blockIdx.x * blockDim.x + threadIdx.x) >> 5;
    const int lane = threadIdx.x & 31;
    if (warp >= E) return;
    const int s = __ldg(es + warp);
    const int d = __ldg(ed + warp);
    const float x = pi_src[s] + pi_dst[d];
    const float g = 1.f / (1.f + __expf(-x));
    const float4 zz = z[(size_t)s * 32 + lane];
    red4(reinterpret_cast<float*>(acc_ih + (size_t)d * 32 + lane),
         g * zz.x, g * zz.y, g * zz.z, g * zz.w);
}

// ---------------------------------------------------------------------------
// Combine: z_out = 0.5*( relu(acc_one/max(deg,1)) + relu(acc_eh*acc_ih) + (a0+a1)*z )
// ---------------------------------------------------------------------------
__global__ void combine_kernel(const float4* __restrict__ acc_one,
                               const float4* __restrict__ acc_eh,
                               const float4* __restrict__ acc_ih,
                               const float* __restrict__ deg,
                               const float2* __restrict__ nalpha,
                               const float4* __restrict__ z,
                               float4* __restrict__ zout, int n_dst)
{
    const int i = blockIdx.x * blockDim.x + threadIdx.x;
    if (i >= n_dst * 32) return;
    const int node = i >> 5;
    const float invd = 1.f / fmaxf(deg[node], 1.f);
    const float2 na = nalpha[node];
    const float nz = na.x + na.y;
    const float4 o  = acc_one[i];
    const float4 eh = acc_eh[i];
    const float4 ih = acc_ih[i];
    const float4 zz = z[i];
    float4 r;
    r.x = 0.5f * (fmaxf(o.x * invd, 0.f) + fmaxf(eh.x * ih.x, 0.f) + nz * zz.x);
    r.y = 0.5f * (fmaxf(o.y * invd, 0.f) + fmaxf(eh.y * ih.y, 0.f) + nz * zz.y);
    r.z = 0.5f * (fmaxf(o.z * invd, 0.f) + fmaxf(eh.z * ih.z, 0.f) + nz * zz.z);
    r.w = 0.5f * (fmaxf(o.w * invd, 0.f) + fmaxf(eh.w * ih.w, 0.f) + nz * zz.w);
    zout[i] = r;
}

// ---------------------------------------------------------------------------
// Host launcher
// ---------------------------------------------------------------------------
static void run_layer(const float4* z, const float4* wz,
                      int n_src, int n_dst,
                      const float* na, const float* ea, const float* ia,
                      const int* es, const int* ed, int Ee,
                      const int* is_, const int* id_, int Ei,
                      float4* zout,
                      float4* acc_one, float4* acc_eh, float4* acc_ih,
                      float* deg, float2* pe_src, float2* pe_dst,
                      float* pi_src, float* pi_dst, float2* nalpha)
{
    {
        const int threads = 256;
        const int blocks = (n_src * 32 + threads - 1) / threads;
        proj_kernel<<<blocks, threads>>>(z, n_src, n_dst, na, ea, ia,
                                         pe_src, pe_dst, pi_src, pi_dst, nalpha);
    }
    const size_t accBytes = (size_t)n_dst * 32 * sizeof(float4);
    cudaMemsetAsync(acc_one, 0, accBytes);
    cudaMemsetAsync(acc_eh, 0, accBytes);
    cudaMemsetAsync(acc_ih, 0, accBytes);
    cudaMemsetAsync(deg, 0, (size_t)n_dst * sizeof(float));
    {
        const int threads = 256;
        const int blocks = (Ee + 7) / 8;
        edge_e_kernel<<<blocks, threads>>>(es, ed, Ee, pe_src, pe_dst, wz, z,
                                           acc_one, acc_eh, deg);
    }
    {
        const int threads = 256;
        const int blocks = (Ei + 7) / 8;
        edge_i_kernel<<<blocks, threads>>>(is_, id_, Ei, pi_src, pi_dst, z, acc_ih);
    }
    {
        const int threads = 256;
        const int blocks = (n_dst * 32 + threads - 1) / threads;
        combine_kernel<<<blocks, threads>>>(acc_one, acc_eh, acc_ih, deg, nalpha,
                                            z, zout, n_dst);
    }
}

extern "C" void kernel_launch(void* const* d_in, const int* in_sizes, int n_in,
                              void* d_out, int out_size)
{
    const float* feat = (const float*)d_in[0];
    const int* src0[2] = {(const int*)d_in[1], (const int*)d_in[3]};  // cor, sim
    const int* dst0[2] = {(const int*)d_in[2], (const int*)d_in[4]};
    const int* src1[2] = {(const int*)d_in[5], (const int*)d_in[7]};
    const int* dst1[2] = {(const int*)d_in[6], (const int*)d_in[8]};
    const int E0 = in_sizes[1];
    const int E1 = in_sizes[5];

    const int b = n_in - 14;  // robust to scalar inputs being present or not
    const float* Win  = (const float*)d_in[b + 0];
    const float* b_in = (const float*)d_in[b + 1];
    const float* na1  = (const float*)d_in[b + 2];
    const float* ea1  = (const float*)d_in[b + 3];
    const float* ia1  = (const float*)d_in[b + 4];
    const float* W1   = (const float*)d_in[b + 5];
    const float* b1   = (const float*)d_in[b + 6];
    const float* na2  = (const float*)d_in[b + 7];
    const float* ea2  = (const float*)d_in[b + 8];
    const float* ia2  = (const float*)d_in[b + 9];
    const float* W2   = (const float*)d_in[b + 10];
    const float* b2   = (const float*)d_in[b + 11];
    const float* Wout = (const float*)d_in[b + 12];
    const float* bout = (const float*)d_in[b + 13];

    const int F = in_sizes[b + 0] / (2 * D);  // 256
    const int n_src0 = in_sizes[0] / F;       // 100000
    const int n_dst0 = N_DST0;
    const int n_dst1 = N_DST1;
    const int n_src1 = n_dst0;

    // Resolve scratch symbol addresses
    float4 *z0, *wz, *z1, *z2, *acc_one, *acc_eh, *acc_ih;
    float *deg, *pi_src, *pi_dst;
    float2 *pe_src, *pe_dst, *nalpha;
    cudaGetSymbolAddress((void**)&z0, g_z0);
    cudaGetSymbolAddress((void**)&wz, g_wz);
    cudaGetSymbolAddress((void**)&z1, g_z1);
    cudaGetSymbolAddress((void**)&z2, g_z2);
    cudaGetSymbolAddress((void**)&acc_one, g_acc_one);
    cudaGetSymbolAddress((void**)&acc_eh, g_acc_eh);
    cudaGetSymbolAddress((void**)&acc_ih, g_acc_ih);
    cudaGetSymbolAddress((void**)&deg, g_deg);
    cudaGetSymbolAddress((void**)&pe_src, g_pe_src);
    cudaGetSymbolAddress((void**)&pe_dst, g_pe_dst);
    cudaGetSymbolAddress((void**)&pi_src, g_pi_src);
    cudaGetSymbolAddress((void**)&pi_dst, g_pi_dst);
    cudaGetSymbolAddress((void**)&nalpha, g_nalpha);

    float* out = (float*)d_out;

    for (int m = 0; m < 2; ++m) {
        // z0 = feat @ Win[m] + b_in[m]
        gemm_tf32_kernel<128><<<(n_src0 + 63) / 64, 256>>>(
            feat, Win + (size_t)m * F * D, b_in + (size_t)m * D,
            (float*)z0, n_src0, F);

        // wz = z0 @ W1[m] + b1[m]
        gemm_tf32_kernel<128><<<(n_src0 + 63) / 64, 256>>>(
            (const float*)z0, W1 + (size_t)m * D * D, b1 + (size_t)m * D,
            (float*)wz, n_src0, D);

        // Layer 1 (graph 0): e-channel = mode edge list, i-channel = other one
        run_layer(z0, wz, n_src0, n_dst0,
                  na1 + (size_t)m * D * 2, ea1 + (size_t)m * 2 * D * 2,
                  ia1 + (size_t)m * 2 * D,
                  src0[m], dst0[m], E0, src0[1 - m], dst0[1 - m], E0,
                  z1, acc_one, acc_eh, acc_ih, deg,
                  pe_src, pe_dst, pi_src, pi_dst, nalpha);

        // wz = z1 @ W2[m] + b2[m]
        gemm_tf32_kernel<128><<<(n_src1 + 63) / 64, 256>>>(
            (const float*)z1, W2 + (size_t)m * D * D, b2 + (size_t)m * D,
            (float*)wz, n_src1, D);

        // Layer 2 (graph 1)
        run_layer(z1, wz, n_src1, n_dst1,
                  na2 + (size_t)m * D * 2, ea2 + (size_t)m * 2 * D * 2,
                  ia2 + (size_t)m * 2 * D,
                  src1[m], dst1[m], E1, src1[1 - m], dst1[1 - m], E1,
                  z2, acc_one, acc_eh, acc_ih, deg,
                  pe_src, pe_dst, pi_src, pi_dst, nalpha);

        // out[m] = z2 @ Wout[m] + bout[m]
        gemm_tf32_kernel<64><<<(n_dst1 + 63) / 64, 256>>>(
            (const float*)z2, Wout + (size_t)m * D * OUTD, bout + (size_t)m * OUTD,
            out + (size_t)m * n_dst1 * OUTD, n_dst1, D);
    }
    (void)out_size;
}

// round 3
// speedup vs baseline: 1.9937x; 1.3918x over previous
#include <cuda_runtime.h>
#include <mma.h>
#include <cstdint>

using namespace nvcuda;

#define D 128
#define NDST0 25000
#define NDST1 5000
#define OUTD 64

// ---------------------------------------------------------------------------
// Scratch (__device__ globals; no allocation anywhere)
// ---------------------------------------------------------------------------
__device__ float4 g_z0[100000 * 32];
__device__ float4 g_z1[25000 * 32];
__device__ float4 g_z2[5000 * 32];
__device__ float4 g_sone[25000 * 32];   // S_one = sum a0*z[s]
__device__ float4 g_p[25000 * 32];      // P = relu(eh*ih) + nz*z_d
__device__ float  g_sw[25000];          // sum of a0 weights
__device__ float  g_deg[25000];
__device__ float2 g_pe_src[100000];
__device__ float2 g_pe_dst[25000];
__device__ float  g_pi_src[100000];
__device__ float  g_pi_dst[25000];
__device__ float2 g_nalpha[25000];
// CSR scratch (4 lists: g0-cor, g0-sim, g1-cor, g1-sim)
__device__ int g_cnt[25000];
__device__ int g_cur[25000];
__device__ int g_row0[25001];
__device__ int g_row1[25001];
__device__ int g_row2[5001];
__device__ int g_row3[5001];
__device__ int g_col0[500000];
__device__ int g_col1[500000];
__device__ int g_col2[100000];
__device__ int g_col3[100000];

// ---------------------------------------------------------------------------
// CSR build: histogram -> single-block scan -> fill
// ---------------------------------------------------------------------------
__global__ void hist_kernel(const int* __restrict__ dst, int E, int* __restrict__ cnt)
{
    const int i = blockIdx.x * blockDim.x + threadIdx.x;
    if (i < E) atomicAdd(cnt + dst[i], 1);
}

__global__ void scan_kernel(const int* __restrict__ cnt, int* __restrict__ row,
                            int* __restrict__ cur, int n)
{
    __shared__ int part[1024];
    const int t = threadIdx.x;
    const int CH = (n + 1023) / 1024;
    const int base = t * CH;
    int sum = 0;
    for (int i = 0; i < CH; ++i) {
        const int idx = base + i;
        if (idx < n) sum += cnt[idx];
    }
    part[t] = sum;
    __syncthreads();
    for (int off = 1; off < 1024; off <<= 1) {
        int v = 0;
        if (t >= off) v = part[t - off];
        __syncthreads();
        part[t] += v;
        __syncthreads();
    }
    int run = (t == 0) ? 0 : part[t - 1];
    for (int i = 0; i < CH; ++i) {
        const int idx = base + i;
        if (idx < n) {
            row[idx] = run;
            cur[idx] = run;
            run += cnt[idx];
        }
    }
    if (t == 1023) row[n] = part[1023];
}

__global__ void fill_kernel(const int* __restrict__ src, const int* __restrict__ dst,
                            int E, int* __restrict__ cur, int* __restrict__ col)
{
    const int i = blockIdx.x * blockDim.x + threadIdx.x;
    if (i < E) {
        const int pos = atomicAdd(cur + dst[i], 1);
        col[pos] = src[i];
    }
}

// ---------------------------------------------------------------------------
// Per-node attention projections: one warp per node.
// ---------------------------------------------------------------------------
__global__ void proj_kernel(const float4* __restrict__ z, int n_src, int n_dst,
                            const float* __restrict__ na,   // [128,2]
                            const float* __restrict__ ea,   // [256,2]
                            const float* __restrict__ ia,   // [256,1]
                            float2* __restrict__ pe_src, float2* __restrict__ pe_dst,
                            float* __restrict__ pi_src, float* __restrict__ pi_dst,
                            float2* __restrict__ nalpha)
{
    const int warp = (blockIdx.x * blockDim.x + threadIdx.x) >> 5;
    const int lane = threadIdx.x & 31;
    if (warp >= n_src) return;

    const float4 z4 = z[(size_t)warp * 32 + lane];

    const float4* ea4 = reinterpret_cast<const float4*>(ea);
    const float4 e0 = ea4[lane * 2 + 0];
    const float4 e1 = ea4[lane * 2 + 1];
    float pes0 = z4.x * e0.x + z4.y * e0.z + z4.z * e1.x + z4.w * e1.z;
    float pes1 = z4.x * e0.y + z4.y * e0.w + z4.z * e1.y + z4.w * e1.w;

    const float4 d0 = ea4[64 + lane * 2 + 0];
    const float4 d1 = ea4[64 + lane * 2 + 1];
    float ped0 = z4.x * d0.x + z4.y * d0.z + z4.z * d1.x + z4.w * d1.z;
    float ped1 = z4.x * d0.y + z4.y * d0.w + z4.z * d1.y + z4.w * d1.w;

    const float4 i0 = *reinterpret_cast<const float4*>(ia + lane * 4);
    float pis = z4.x * i0.x + z4.y * i0.y + z4.z * i0.z + z4.w * i0.w;
    const float4 i1 = *reinterpret_cast<const float4*>(ia + 128 + lane * 4);
    float pid = z4.x * i1.x + z4.y * i1.y + z4.z * i1.z + z4.w * i1.w;

    const float4* na4 = reinterpret_cast<const float4*>(na);
    const float4 n0 = na4[lane * 2 + 0];
    const float4 n1 = na4[lane * 2 + 1];
    float nl0 = z4.x * n0.x + z4.y * n0.z + z4.z * n1.x + z4.w * n1.z;
    float nl1 = z4.x * n0.y + z4.y * n0.w + z4.z * n1.y + z4.w * n1.w;

#pragma unroll
    for (int off = 16; off; off >>= 1) {
        pes0 += __shfl_xor_sync(0xffffffffu, pes0, off);
        pes1 += __shfl_xor_sync(0xffffffffu, pes1, off);
        ped0 += __shfl_xor_sync(0xffffffffu, ped0, off);
        ped1 += __shfl_xor_sync(0xffffffffu, ped1, off);
        pis  += __shfl_xor_sync(0xffffffffu, pis, off);
        pid  += __shfl_xor_sync(0xffffffffu, pid, off);
        nl0  += __shfl_xor_sync(0xffffffffu, nl0, off);
        nl1  += __shfl_xor_sync(0xffffffffu, nl1, off);
    }

    if (lane == 0) {
        pe_src[warp] = make_float2(pes0, pes1);
        pi_src[warp] = pis;
        if (warp < n_dst) {
            pe_dst[warp] = make_float2(ped0, ped1);
            pi_dst[warp] = pid;
            const float mx = fmaxf(nl0, nl1);
            const float a  = __expf(nl0 - mx);
            const float b  = __expf(nl1 - mx);
            const float inv = 1.f / (a + b);
            nalpha[warp] = make_float2(a * inv, b * inv);
        }
    }
}

// ---------------------------------------------------------------------------
// Fused aggregation: one warp per dst node. CSR gather, register accumulate.
//   S_one = sum_e a0 * z[s]          (e-channel)
//   eh    = sum_e a1 * z[s]          (e-channel)
//   ih    = sum_i g  * z[s]          (i-channel)
//   P     = relu(eh*ih) + (na0+na1) * z[d]
//   sw    = sum_e a0,  deg = #e-edges
// ---------------------------------------------------------------------------
__global__ void agg_kernel(int n_dst,
                           const int* __restrict__ rowe, const int* __restrict__ cole,
                           const int* __restrict__ rowi, const int* __restrict__ coli,
                           const float2* __restrict__ pe_src, const float2* __restrict__ pe_dst,
                           const float* __restrict__ pi_src, const float* __restrict__ pi_dst,
                           const float2* __restrict__ nalpha,
                           const float4* __restrict__ z,
                           float4* __restrict__ S_one, float4* __restrict__ P,
                           float* __restrict__ sw_out, float* __restrict__ deg_out)
{
    const int d    = (blockIdx.x * blockDim.x + threadIdx.x) >> 5;
    const int lane = threadIdx.x & 31;
    if (d >= n_dst) return;

    float4 acc1 = make_float4(0.f, 0.f, 0.f, 0.f);
    float4 acce = make_float4(0.f, 0.f, 0.f, 0.f);
    float4 acci = make_float4(0.f, 0.f, 0.f, 0.f);
    float  sw   = 0.f;

    // ---- e-channel ----
    const float2 pd = pe_dst[d];
    const int re0 = rowe[d], re1 = rowe[d + 1];
    for (int c = re0; c < re1; c += 32) {
        const int nvalid = min(32, re1 - c);
        int   s  = 0;
        float a0 = 0.f, a1 = 0.f;
        if (lane < nvalid) {
            s = cole[c + lane];
            const float2 ps = pe_src[s];
            const float l0 = ps.x + pd.x, l1 = ps.y + pd.y;
            const float mx = fmaxf(l0, l1);
            const float x0 = __expf(l0 - mx), x1 = __expf(l1 - mx);
            const float inv = 1.f / (x0 + x1);
            a0 = x0 * inv;
            a1 = x1 * inv;
            sw += a0;
        }
#pragma unroll 4
        for (int j = 0; j < nvalid; ++j) {
            const int   sj = __shfl_sync(0xffffffffu, s,  j);
            const float w0 = __shfl_sync(0xffffffffu, a0, j);
            const float w1 = __shfl_sync(0xffffffffu, a1, j);
            const float4 z4 = z[(size_t)sj * 32 + lane];
            acc1.x += w0 * z4.x; acc1.y += w0 * z4.y; acc1.z += w0 * z4.z; acc1.w += w0 * z4.w;
            acce.x += w1 * z4.x; acce.y += w1 * z4.y; acce.z += w1 * z4.z; acce.w += w1 * z4.w;
        }
    }

    // ---- i-channel ----
    const float pid = pi_dst[d];
    const int ri0 = rowi[d], ri1 = rowi[d + 1];
    for (int c = ri0; c < ri1; c += 32) {
        const int nvalid = min(32, ri1 - c);
        int   s = 0;
        float g = 0.f;
        if (lane < nvalid) {
            s = coli[c + lane];
            const float x = pi_src[s] + pid;
            g = 1.f / (1.f + __expf(-x));
        }
#pragma unroll 4
        for (int j = 0; j < nvalid; ++j) {
            const int   sj = __shfl_sync(0xffffffffu, s, j);
            const float w  = __shfl_sync(0xffffffffu, g, j);
            const float4 z4 = z[(size_t)sj * 32 + lane];
            acci.x += w * z4.x; acci.y += w * z4.y; acci.z += w * z4.z; acci.w += w * z4.w;
        }
    }

#pragma unroll
    for (int off = 16; off; off >>= 1)
        sw += __shfl_xor_sync(0xffffffffu, sw, off);

    const float2 na = nalpha[d];
    const float  nz = na.x + na.y;
    const float4 zd = z[(size_t)d * 32 + lane];
    float4 p;
    p.x = fmaxf(acce.x * acci.x, 0.f) + nz * zd.x;
    p.y = fmaxf(acce.y * acci.y, 0.f) + nz * zd.y;
    p.z = fmaxf(acce.z * acci.z, 0.f) + nz * zd.z;
    p.w = fmaxf(acce.w * acci.w, 0.f) + nz * zd.w;

    S_one[(size_t)d * 32 + lane] = acc1;
    P[(size_t)d * 32 + lane]     = p;
    if (lane == 0) {
        sw_out[d]  = sw;
        deg_out[d] = (float)(re1 - re0);
    }
}

// ---------------------------------------------------------------------------
// TF32 tensor-core GEMM: C[M,BN] = A[M,K] @ B[K,BN], epilogue either
//   bias add (FUSED=false) or the layer combine (FUSED=true):
//   C = 0.5*( relu((T + sw*b) / max(deg,1)) + P )
// ---------------------------------------------------------------------------
template <int BN, bool FUSED>
__global__ void gemm_tf32_kernel(const float* __restrict__ A,
                                 const float* __restrict__ B,
                                 const float* __restrict__ bias,
                                 float* __restrict__ C,
                                 int M, int K,
                                 const float* __restrict__ P,
                                 const float* __restrict__ sw,
                                 const float* __restrict__ deg)
{
    constexpr int BM  = 64, BK = 16;
    constexpr int BNP = BN + 8;
    constexpr int WN  = BN / 4;
    constexpr int FN  = WN / 16;
    constexpr int FM  = 2;

    __shared__ float sbuf[BM * BNP];
    float* As = sbuf;
    float* Bs = sbuf + BM * BK;

    const int tid    = threadIdx.x;
    const int warp   = tid >> 5;
    const int warp_m = warp & 1;
    const int warp_n = warp >> 1;
    const int m0     = blockIdx.x * BM;

    wmma::fragment<wmma::accumulator, 16, 16, 8, float> acc[FM][FN];
#pragma unroll
    for (int i = 0; i < FM; ++i)
#pragma unroll
        for (int j = 0; j < FN; ++j) wmma::fill_fragment(acc[i][j], 0.f);

    for (int k0 = 0; k0 < K; k0 += BK) {
        {
            const int row = tid >> 2;
            const int cc  = (tid & 3) * 4;
            float4 a = make_float4(0.f, 0.f, 0.f, 0.f);
            if (m0 + row < M)
                a = *reinterpret_cast<const float4*>(A + (size_t)(m0 + row) * K + k0 + cc);
            *reinterpret_cast<float4*>(As + row * BK + cc) = a;
        }
#pragma unroll
        for (int i = tid; i < BK * BN / 4; i += 256) {
            const int row = i / (BN / 4);
            const int cc  = (i % (BN / 4)) * 4;
            *reinterpret_cast<float4*>(Bs + row * BNP + cc) =
                *reinterpret_cast<const float4*>(B + (size_t)(k0 + row) * BN + cc);
        }
        __syncthreads();

#pragma unroll
        for (int ks = 0; ks < 2; ++ks) {
            wmma::fragment<wmma::matrix_a, 16, 16, 8, wmma::precision::tf32, wmma::row_major> af[FM];
            wmma::fragment<wmma::matrix_b, 16, 16, 8, wmma::precision::tf32, wmma::row_major> bf[FN];
#pragma unroll
            for (int i = 0; i < FM; ++i) {
                wmma::load_matrix_sync(af[i], As + (warp_m * 32 + i * 16) * BK + ks * 8, BK);
#pragma unroll
                for (int e = 0; e < af[i].num_elements; ++e)
                    af[i].x[e] = wmma::__float_to_tf32(af[i].x[e]);
            }
#pragma unroll
            for (int j = 0; j < FN; ++j) {
                wmma::load_matrix_sync(bf[j], Bs + (ks * 8) * BNP + warp_n * WN + j * 16, BNP);
#pragma unroll
                for (int e = 0; e < bf[j].num_elements; ++e)
                    bf[j].x[e] = wmma::__float_to_tf32(bf[j].x[e]);
            }
#pragma unroll
            for (int i = 0; i < FM; ++i)
#pragma unroll
                for (int j = 0; j < FN; ++j)
                    wmma::mma_sync(acc[i][j], af[i], bf[j], acc[i][j]);
        }
        __syncthreads();
    }

    float* Cs = sbuf;
#pragma unroll
    for (int i = 0; i < FM; ++i)
#pragma unroll
        for (int j = 0; j < FN; ++j)
            wmma::store_matrix_sync(Cs + (warp_m * 32 + i * 16) * BNP + warp_n * WN + j * 16,
                                    acc[i][j], BNP, wmma::mem_row_major);
    __syncthreads();

#pragma unroll
    for (int i = tid; i < BM * BN / 4; i += 256) {
        const int row = i / (BN / 4);
        const int cc  = (i % (BN / 4)) * 4;
        const int grow = m0 + row;
        if (grow < M) {
            float4 v = *reinterpret_cast<const float4*>(Cs + row * BNP + cc);
            const float4 bb = *reinterpret_cast<const float4*>(bias + cc);
            if (FUSED) {
                const float swv  = sw[grow];
                const float invd = 1.f / fmaxf(deg[grow], 1.f);
                const float4 pp  = *reinterpret_cast<const float4*>(P + (size_t)grow * BN + cc);
                v.x = 0.5f * (fmaxf((v.x + swv * bb.x) * invd, 0.f) + pp.x);
                v.y = 0.5f * (fmaxf((v.y + swv * bb.y) * invd, 0.f) + pp.y);
                v.z = 0.5f * (fmaxf((v.z + swv * bb.z) * invd, 0.f) + pp.z);
                v.w = 0.5f * (fmaxf((v.w + swv * bb.w) * invd, 0.f) + pp.w);
            } else {
                v.x += bb.x; v.y += bb.y; v.z += bb.z; v.w += bb.w;
            }
            *reinterpret_cast<float4*>(C + (size_t)grow * BN + cc) = v;
        }
    }
}

// ---------------------------------------------------------------------------
// Host side
// ---------------------------------------------------------------------------
extern "C" void kernel_launch(void* const* d_in, const int* in_sizes, int n_in,
                              void* d_out, int out_size)
{
    const float* feat = (const float*)d_in[0];
    const int* src0[2] = {(const int*)d_in[1], (const int*)d_in[3]};  // cor, sim
    const int* dst0[2] = {(const int*)d_in[2], (const int*)d_in[4]};
    const int* src1[2] = {(const int*)d_in[5], (const int*)d_in[7]};
    const int* dst1[2] = {(const int*)d_in[6], (const int*)d_in[8]};
    const int E0 = in_sizes[1];
    const int E1 = in_sizes[5];

    const int b = n_in - 14;
    const float* Win  = (const float*)d_in[b + 0];
    const float* b_in = (const float*)d_in[b + 1];
    const float* na1  = (const float*)d_in[b + 2];
    const float* ea1  = (const float*)d_in[b + 3];
    const float* ia1  = (const float*)d_in[b + 4];
    const float* W1   = (const float*)d_in[b + 5];
    const float* b1   = (const float*)d_in[b + 6];
    const float* na2  = (const float*)d_in[b + 7];
    const float* ea2  = (const float*)d_in[b + 8];
    const float* ia2  = (const float*)d_in[b + 9];
    const float* W2   = (const float*)d_in[b + 10];
    const float* b2   = (const float*)d_in[b + 11];
    const float* Wout = (const float*)d_in[b + 12];
    const float* bout = (const float*)d_in[b + 13];

    const int F = in_sizes[b + 0] / (2 * D);  // 256
    const int n_src0 = in_sizes[0] / F;       // 100000
    const int n_dst0 = NDST0;
    const int n_dst1 = NDST1;
    const int n_src1 = n_dst0;

    float4 *z0, *z1, *z2, *sone, *P4;
    float *sw, *deg, *pi_src, *pi_dst;
    float2 *pe_src, *pe_dst, *nalpha;
    int *cnt, *cur, *row[4], *col[4];
    cudaGetSymbolAddress((void**)&z0, g_z0);
    cudaGetSymbolAddress((void**)&z1, g_z1);
    cudaGetSymbolAddress((void**)&z2, g_z2);
    cudaGetSymbolAddress((void**)&sone, g_sone);
    cudaGetSymbolAddress((void**)&P4, g_p);
    cudaGetSymbolAddress((void**)&sw, g_sw);
    cudaGetSymbolAddress((void**)&deg, g_deg);
    cudaGetSymbolAddress((void**)&pe_src, g_pe_src);
    cudaGetSymbolAddress((void**)&pe_dst, g_pe_dst);
    cudaGetSymbolAddress((void**)&pi_src, g_pi_src);
    cudaGetSymbolAddress((void**)&pi_dst, g_pi_dst);
    cudaGetSymbolAddress((void**)&nalpha, g_nalpha);
    cudaGetSymbolAddress((void**)&cnt, g_cnt);
    cudaGetSymbolAddress((void**)&cur, g_cur);
    cudaGetSymbolAddress((void**)&row[0], g_row0);
    cudaGetSymbolAddress((void**)&row[1], g_row1);
    cudaGetSymbolAddress((void**)&row[2], g_row2);
    cudaGetSymbolAddress((void**)&row[3], g_row3);
    cudaGetSymbolAddress((void**)&col[0], g_col0);
    cudaGetSymbolAddress((void**)&col[1], g_col1);
    cudaGetSymbolAddress((void**)&col[2], g_col2);
    cudaGetSymbolAddress((void**)&col[3], g_col3);

    // ---- Build 4 CSRs (mode-independent) ----
    const int* srcs[4] = {src0[0], src0[1], src1[0], src1[1]};
    const int* dsts[4] = {dst0[0], dst0[1], dst1[0], dst1[1]};
    const int  Es[4]   = {E0, E0, E1, E1};
    const int  Ns[4]   = {n_dst0, n_dst0, n_dst1, n_dst1};
    for (int l = 0; l < 4; ++l) {
        cudaMemsetAsync(cnt, 0, (size_t)Ns[l] * sizeof(int));
        hist_kernel<<<(Es[l] + 255) / 256, 256>>>(dsts[l], Es[l], cnt);
        scan_kernel<<<1, 1024>>>(cnt, row[l], cur, Ns[l]);
        fill_kernel<<<(Es[l] + 255) / 256, 256>>>(srcs[l], dsts[l], Es[l], cur, col[l]);
    }

    float* out = (float*)d_out;

    for (int m = 0; m < 2; ++m) {
        // z0 = feat @ Win[m] + b_in[m]
        gemm_tf32_kernel<128, false><<<(n_src0 + 63) / 64, 256>>>(
            feat, Win + (size_t)m * F * D, b_in + (size_t)m * D,
            (float*)z0, n_src0, F, nullptr, nullptr, nullptr);

        // ---- Layer 1 on graph 0 ----
        proj_kernel<<<(n_src0 * 32 + 255) / 256, 256>>>(
            z0, n_src0, n_dst0,
            na1 + (size_t)m * D * 2, ea1 + (size_t)m * 2 * D * 2, ia1 + (size_t)m * 2 * D,
            pe_src, pe_dst, pi_src, pi_dst, nalpha);

        agg_kernel<<<(n_dst0 * 32 + 255) / 256, 256>>>(
            n_dst0, row[m], col[m], row[1 - m], col[1 - m],
            pe_src, pe_dst, pi_src, pi_dst, nalpha, z0,
            sone, P4, sw, deg);

        gemm_tf32_kernel<128, true><<<(n_dst0 + 63) / 64, 256>>>(
            (const float*)sone, W1 + (size_t)m * D * D, b1 + (size_t)m * D,
            (float*)z1, n_dst0, D, (const float*)P4, sw, deg);

        // ---- Layer 2 on graph 1 ----
        proj_kernel<<<(n_src1 * 32 + 255) / 256, 256>>>(
            z1, n_src1, n_dst1,
            na2 + (size_t)m * D * 2, ea2 + (size_t)m * 2 * D * 2, ia2 + (size_t)m * 2 * D,
            pe_src, pe_dst, pi_src, pi_dst, nalpha);

        agg_kernel<<<(n_dst1 * 32 + 255) / 256, 256>>>(
            n_dst1, row[2 + m], col[2 + m], row[2 + (1 - m)], col[2 + (1 - m)],
            pe_src, pe_dst, pi_src, pi_dst, nalpha, z1,
            sone, P4, sw, deg);

        gemm_tf32_kernel<128, true><<<(n_dst1 + 63) / 64, 256>>>(
            (const float*)sone, W2 + (size_t)m * D * D, b2 + (size_t)m * D,
            (float*)z2, n_dst1, D, (const float*)P4, sw, deg);

        // out[m] = z2 @ Wout[m] + bout[m]
        gemm_tf32_kernel<64, false><<<(n_dst1 + 63) / 64, 256>>>(
            (const float*)z2, Wout + (size_t)m * D * OUTD, bout + (size_t)m * OUTD,
            out + (size_t)m * n_dst1 * OUTD, n_dst1, D, nullptr, nullptr, nullptr);
    }
    (void)out_size;
}

// round 4
// speedup vs baseline: 2.2545x; 1.1308x over previous
#include <cuda_runtime.h>
#include <mma.h>
#include <cstdint>

using namespace nvcuda;

#define D 128
#define NDST0 25000
#define NDST1 5000
#define OUTD 64

// ---------------------------------------------------------------------------
// Scratch (__device__ globals; no allocation anywhere)
// ---------------------------------------------------------------------------
__device__ float4 g_z0[100000 * 32];
__device__ float4 g_z1[25000 * 32];
__device__ float4 g_z2[5000 * 32];
__device__ float4 g_sone[25000 * 32];   // S_one = sum a0*z[s]
__device__ float4 g_p[25000 * 32];      // P = relu(eh*ih) + nz*z_d
__device__ float  g_sw[25000];
__device__ float  g_deg[25000];
__device__ float2 g_pe_src[100000];
__device__ float2 g_pe_dst[25000];
__device__ float  g_pi_src[100000];
__device__ float  g_pi_dst[25000];
__device__ float2 g_nalpha[25000];
// CSR scratch: counts/cursors for 4 lists packed [0,N0,2N0,2N0+N1]
__device__ int g_cnt[2 * NDST0 + 2 * NDST1];
__device__ int g_cur[2 * NDST0 + 2 * NDST1];
__device__ int g_row0[NDST0 + 1];
__device__ int g_row1[NDST0 + 1];
__device__ int g_row2[NDST1 + 1];
__device__ int g_row3[NDST1 + 1];
__device__ int g_col0[500000];
__device__ int g_col1[500000];
__device__ int g_col2[100000];
__device__ int g_col3[100000];

// ---------------------------------------------------------------------------
// cp.async helpers
// ---------------------------------------------------------------------------
__device__ __forceinline__ void cp_async16(float* smem, const float* gmem)
{
    uint32_t s = (uint32_t)__cvta_generic_to_shared(smem);
    asm volatile("cp.async.cg.shared.global [%0], [%1], 16;" :: "r"(s), "l"(gmem));
}
__device__ __forceinline__ void cp_commit() { asm volatile("cp.async.commit_group;"); }
__device__ __forceinline__ void cp_wait1()  { asm volatile("cp.async.wait_group 1;"); }
__device__ __forceinline__ void cp_wait0()  { asm volatile("cp.async.wait_group 0;"); }

// ---------------------------------------------------------------------------
// Batched CSR build: one memset + 3 launches for all 4 edge lists
// list l: dst list, cnt offset CO[l], n nodes NS[l]
// ---------------------------------------------------------------------------
__global__ void hist4_kernel(const int* __restrict__ d0, const int* __restrict__ d1,
                             const int* __restrict__ d2, const int* __restrict__ d3,
                             int E0, int E1, int* __restrict__ cnt)
{
    const int i = blockIdx.x * blockDim.x + threadIdx.x;
    const int t0 = E0, t1 = 2 * E0, t2 = 2 * E0 + E1, t3 = 2 * E0 + 2 * E1;
    if (i < t0)      atomicAdd(cnt + d0[i], 1);
    else if (i < t1) atomicAdd(cnt + NDST0 + d1[i - t0], 1);
    else if (i < t2) atomicAdd(cnt + 2 * NDST0 + d2[i - t1], 1);
    else if (i < t3) atomicAdd(cnt + 2 * NDST0 + NDST1 + d3[i - t2], 1);
}

__global__ void scan4_kernel(const int* __restrict__ cnt, int* __restrict__ cur,
                             int* __restrict__ row0, int* __restrict__ row1,
                             int* __restrict__ row2, int* __restrict__ row3)
{
    __shared__ int part[1024];
    const int b = blockIdx.x;
    const int n = (b < 2) ? NDST0 : NDST1;
    const int off = (b == 0) ? 0 : (b == 1) ? NDST0 : (b == 2) ? 2 * NDST0 : 2 * NDST0 + NDST1;
    int* row = (b == 0) ? row0 : (b == 1) ? row1 : (b == 2) ? row2 : row3;
    const int t = threadIdx.x;
    const int CH = (n + 1023) / 1024;
    const int base = t * CH;
    int sum = 0;
    for (int i = 0; i < CH; ++i) {
        const int idx = base + i;
        if (idx < n) sum += cnt[off + idx];
    }
    part[t] = sum;
    __syncthreads();
    for (int o = 1; o < 1024; o <<= 1) {
        int v = 0;
        if (t >= o) v = part[t - o];
        __syncthreads();
        part[t] += v;
        __syncthreads();
    }
    int run = (t == 0) ? 0 : part[t - 1];
    for (int i = 0; i < CH; ++i) {
        const int idx = base + i;
        if (idx < n) {
            row[idx] = run;
            cur[off + idx] = run;
            run += cnt[off + idx];
        }
    }
    if (t == 1023) row[n] = part[1023];
}

__global__ void fill4_kernel(const int* __restrict__ s0, const int* __restrict__ d0,
                             const int* __restrict__ s1, const int* __restrict__ d1,
                             const int* __restrict__ s2, const int* __restrict__ d2,
                             const int* __restrict__ s3, const int* __restrict__ d3,
                             int E0, int E1, int* __restrict__ cur,
                             int* __restrict__ c0, int* __restrict__ c1,
                             int* __restrict__ c2, int* __restrict__ c3)
{
    const int i = blockIdx.x * blockDim.x + threadIdx.x;
    const int t0 = E0, t1 = 2 * E0, t2 = 2 * E0 + E1, t3 = 2 * E0 + 2 * E1;
    if (i < t0)      { const int p = atomicAdd(cur + d0[i], 1);                       c0[p] = s0[i]; }
    else if (i < t1) { const int j = i - t0; const int p = atomicAdd(cur + NDST0 + d1[j], 1);            c1[p] = s1[j]; }
    else if (i < t2) { const int j = i - t1; const int p = atomicAdd(cur + 2 * NDST0 + d2[j], 1);        c2[p] = s2[j]; }
    else if (i < t3) { const int j = i - t2; const int p = atomicAdd(cur + 2 * NDST0 + NDST1 + d3[j], 1); c3[p] = s3[j]; }
}

// ---------------------------------------------------------------------------
// Per-node attention projections: one warp per node.
// ---------------------------------------------------------------------------
__global__ void proj_kernel(const float4* __restrict__ z, int n_src, int n_dst,
                            const float* __restrict__ na,   // [128,2]
                            const float* __restrict__ ea,   // [256,2]
                            const float* __restrict__ ia,   // [256,1]
                            float2* __restrict__ pe_src, float2* __restrict__ pe_dst,
                            float* __restrict__ pi_src, float* __restrict__ pi_dst,
                            float2* __restrict__ nalpha)
{
    const int warp = (blockIdx.x * blockDim.x + threadIdx.x) >> 5;
    const int lane = threadIdx.x & 31;
    if (warp >= n_src) return;

    const float4 z4 = z[(size_t)warp * 32 + lane];

    const float4* ea4 = reinterpret_cast<const float4*>(ea);
    const float4 e0 = ea4[lane * 2 + 0];
    const float4 e1 = ea4[lane * 2 + 1];
    float pes0 = z4.x * e0.x + z4.y * e0.z + z4.z * e1.x + z4.w * e1.z;
    float pes1 = z4.x * e0.y + z4.y * e0.w + z4.z * e1.y + z4.w * e1.w;

    const float4 d0 = ea4[64 + lane * 2 + 0];
    const float4 d1 = ea4[64 + lane * 2 + 1];
    float ped0 = z4.x * d0.x + z4.y * d0.z + z4.z * d1.x + z4.w * d1.z;
    float ped1 = z4.x * d0.y + z4.y * d0.w + z4.z * d1.y + z4.w * d1.w;

    const float4 i0 = *reinterpret_cast<const float4*>(ia + lane * 4);
    float pis = z4.x * i0.x + z4.y * i0.y + z4.z * i0.z + z4.w * i0.w;
    const float4 i1 = *reinterpret_cast<const float4*>(ia + 128 + lane * 4);
    float pid = z4.x * i1.x + z4.y * i1.y + z4.z * i1.z + z4.w * i1.w;

    const float4* na4 = reinterpret_cast<const float4*>(na);
    const float4 n0 = na4[lane * 2 + 0];
    const float4 n1 = na4[lane * 2 + 1];
    float nl0 = z4.x * n0.x + z4.y * n0.z + z4.z * n1.x + z4.w * n1.z;
    float nl1 = z4.x * n0.y + z4.y * n0.w + z4.z * n1.y + z4.w * n1.w;

#pragma unroll
    for (int off = 16; off; off >>= 1) {
        pes0 += __shfl_xor_sync(0xffffffffu, pes0, off);
        pes1 += __shfl_xor_sync(0xffffffffu, pes1, off);
        ped0 += __shfl_xor_sync(0xffffffffu, ped0, off);
        ped1 += __shfl_xor_sync(0xffffffffu, ped1, off);
        pis  += __shfl_xor_sync(0xffffffffu, pis, off);
        pid  += __shfl_xor_sync(0xffffffffu, pid, off);
        nl0  += __shfl_xor_sync(0xffffffffu, nl0, off);
        nl1  += __shfl_xor_sync(0xffffffffu, nl1, off);
    }

    if (lane == 0) {
        pe_src[warp] = make_float2(pes0, pes1);
        pi_src[warp] = pis;
        if (warp < n_dst) {
            pe_dst[warp] = make_float2(ped0, ped1);
            pi_dst[warp] = pid;
            const float mx = fmaxf(nl0, nl1);
            const float a  = __expf(nl0 - mx);
            const float b  = __expf(nl1 - mx);
            const float inv = 1.f / (a + b);
            nalpha[warp] = make_float2(a * inv, b * inv);
        }
    }
}

// ---------------------------------------------------------------------------
// Fused aggregation: one warp per dst node (unchanged from round 3)
// ---------------------------------------------------------------------------
__global__ void agg_kernel(int n_dst,
                           const int* __restrict__ rowe, const int* __restrict__ cole,
                           const int* __restrict__ rowi, const int* __restrict__ coli,
                           const float2* __restrict__ pe_src, const float2* __restrict__ pe_dst,
                           const float* __restrict__ pi_src, const float* __restrict__ pi_dst,
                           const float2* __restrict__ nalpha,
                           const float4* __restrict__ z,
                           float4* __restrict__ S_one, float4* __restrict__ P,
                           float* __restrict__ sw_out, float* __restrict__ deg_out)
{
    const int d    = (blockIdx.x * blockDim.x + threadIdx.x) >> 5;
    const int lane = threadIdx.x & 31;
    if (d >= n_dst) return;

    float4 acc1 = make_float4(0.f, 0.f, 0.f, 0.f);
    float4 acce = make_float4(0.f, 0.f, 0.f, 0.f);
    float4 acci = make_float4(0.f, 0.f, 0.f, 0.f);
    float  sw   = 0.f;

    const float2 pd = pe_dst[d];
    const int re0 = rowe[d], re1 = rowe[d + 1];
    for (int c = re0; c < re1; c += 32) {
        const int nvalid = min(32, re1 - c);
        int   s  = 0;
        float a0 = 0.f, a1 = 0.f;
        if (lane < nvalid) {
            s = cole[c + lane];
            const float2 ps = pe_src[s];
            const float l0 = ps.x + pd.x, l1 = ps.y + pd.y;
            const float mx = fmaxf(l0, l1);
            const float x0 = __expf(l0 - mx), x1 = __expf(l1 - mx);
            const float inv = 1.f / (x0 + x1);
            a0 = x0 * inv;
            a1 = x1 * inv;
            sw += a0;
        }
#pragma unroll 4
        for (int j = 0; j < nvalid; ++j) {
            const int   sj = __shfl_sync(0xffffffffu, s,  j);
            const float w0 = __shfl_sync(0xffffffffu, a0, j);
            const float w1 = __shfl_sync(0xffffffffu, a1, j);
            const float4 z4 = z[(size_t)sj * 32 + lane];
            acc1.x += w0 * z4.x; acc1.y += w0 * z4.y; acc1.z += w0 * z4.z; acc1.w += w0 * z4.w;
            acce.x += w1 * z4.x; acce.y += w1 * z4.y; acce.z += w1 * z4.z; acce.w += w1 * z4.w;
        }
    }

    const float pid = pi_dst[d];
    const int ri0 = rowi[d], ri1 = rowi[d + 1];
    for (int c = ri0; c < ri1; c += 32) {
        const int nvalid = min(32, ri1 - c);
        int   s = 0;
        float g = 0.f;
        if (lane < nvalid) {
            s = coli[c + lane];
            const float x = pi_src[s] + pid;
            g = 1.f / (1.f + __expf(-x));
        }
#pragma unroll 4
        for (int j = 0; j < nvalid; ++j) {
            const int   sj = __shfl_sync(0xffffffffu, s, j);
            const float w  = __shfl_sync(0xffffffffu, g, j);
            const float4 z4 = z[(size_t)sj * 32 + lane];
            acci.x += w * z4.x; acci.y += w * z4.y; acci.z += w * z4.z; acci.w += w * z4.w;
        }
    }

#pragma unroll
    for (int off = 16; off; off >>= 1)
        sw += __shfl_xor_sync(0xffffffffu, sw, off);

    const float2 na = nalpha[d];
    const float  nz = na.x + na.y;
    const float4 zd = z[(size_t)d * 32 + lane];
    float4 p;
    p.x = fmaxf(acce.x * acci.x, 0.f) + nz * zd.x;
    p.y = fmaxf(acce.y * acci.y, 0.f) + nz * zd.y;
    p.z = fmaxf(acce.z * acci.z, 0.f) + nz * zd.z;
    p.w = fmaxf(acce.w * acci.w, 0.f) + nz * zd.w;

    S_one[(size_t)d * 32 + lane] = acc1;
    P[(size_t)d * 32 + lane]     = p;
    if (lane == 0) {
        sw_out[d]  = sw;
        deg_out[d] = (float)(re1 - re0);
    }
}

// ---------------------------------------------------------------------------
// Pipelined TF32 GEMM: BM=128, BK=16, 2-stage cp.async double buffering.
// 256 threads = 8 warps (4 along M x 2 along N). Warp tile 32 x (BN/2).
// Epilogue: bias (FUSED=false) or layer combine (FUSED=true).
// ---------------------------------------------------------------------------
template <int BN, bool FUSED>
__global__ void __launch_bounds__(256)
gemm_pipe_kernel(const float* __restrict__ A, const float* __restrict__ B,
                 const float* __restrict__ bias, float* __restrict__ C,
                 int M, int K,
                 const float* __restrict__ P, const float* __restrict__ sw,
                 const float* __restrict__ deg)
{
    constexpr int BM   = 128, BK = 16;
    constexpr int BNP  = BN + 8;
    constexpr int ASZ  = BM * BK;              // 2048
    constexpr int BSZ  = BK * BNP;             // 2176 / 1152
    constexpr int STG  = ASZ + BSZ;
    constexpr int CSZ  = 64 * BNP;             // two-phase C staging
    constexpr int SMSZ = (2 * STG > CSZ) ? 2 * STG : CSZ;
    constexpr int WN   = BN / 2;               // 64 / 32
    constexpr int FN   = WN / 16;              // 4 / 2
    constexpr int FM   = 2;
    constexpr int BLD  = (BN == 128) ? 2 : 1;  // B float4 loads per thread

    __shared__ float sbuf[SMSZ];

    const int tid    = threadIdx.x;
    const int warp   = tid >> 5;
    const int warp_m = warp & 3;
    const int warp_n = warp >> 2;
    const int m0     = blockIdx.x * BM;

    wmma::fragment<wmma::accumulator, 16, 16, 8, float> acc[FM][FN];
#pragma unroll
    for (int i = 0; i < FM; ++i)
#pragma unroll
        for (int j = 0; j < FN; ++j) wmma::fill_fragment(acc[i][j], 0.f);

    // A: 512 float4 -> 2/thread; clamp OOB rows to M-1 (writeout is guarded)
    const int a_row0 = tid >> 2;
    const int a_cc   = (tid & 3) * 4;

    auto load_tiles = [&](int stage, int k0) {
        float* As = sbuf + stage * STG;
        float* Bs = As + ASZ;
#pragma unroll
        for (int i = 0; i < 2; ++i) {
            const int row = a_row0 + i * 64;
            int gr = m0 + row;
            gr = gr < M ? gr : M - 1;
            cp_async16(As + row * BK + a_cc, A + (size_t)gr * K + k0 + a_cc);
        }
#pragma unroll
        for (int i = 0; i < BLD; ++i) {
            const int fidx = tid + i * 256;
            const int row  = fidx / (BN / 4);
            const int cc   = (fidx % (BN / 4)) * 4;
            cp_async16(Bs + row * BNP + cc, B + (size_t)(k0 + row) * BN + cc);
        }
        cp_commit();
    };

    const int NT = K / BK;
    load_tiles(0, 0);

    for (int t = 0; t < NT; ++t) {
        const int st = t & 1;
        if (t + 1 < NT) {
            load_tiles(st ^ 1, (t + 1) * BK);
            cp_wait1();
        } else {
            cp_wait0();
        }
        __syncthreads();

        const float* As = sbuf + st * STG;
        const float* Bs = As + ASZ;
#pragma unroll
        for (int ks = 0; ks < 2; ++ks) {
            wmma::fragment<wmma::matrix_a, 16, 16, 8, wmma::precision::tf32, wmma::row_major> af[FM];
            wmma::fragment<wmma::matrix_b, 16, 16, 8, wmma::precision::tf32, wmma::row_major> bf[FN];
#pragma unroll
            for (int i = 0; i < FM; ++i) {
                wmma::load_matrix_sync(af[i], As + (warp_m * 32 + i * 16) * BK + ks * 8, BK);
#pragma unroll
                for (int e = 0; e < af[i].num_elements; ++e)
                    af[i].x[e] = wmma::__float_to_tf32(af[i].x[e]);
            }
#pragma unroll
            for (int j = 0; j < FN; ++j) {
                wmma::load_matrix_sync(bf[j], Bs + (ks * 8) * BNP + warp_n * WN + j * 16, BNP);
#pragma unroll
                for (int e = 0; e < bf[j].num_elements; ++e)
                    bf[j].x[e] = wmma::__float_to_tf32(bf[j].x[e]);
            }
#pragma unroll
            for (int i = 0; i < FM; ++i)
#pragma unroll
                for (int j = 0; j < FN; ++j)
                    wmma::mma_sync(acc[i][j], af[i], bf[j], acc[i][j]);
        }
        __syncthreads();
    }

    // ---- two-phase staged writeout (64 rows per phase) ----
    float* Cs = sbuf;
#pragma unroll
    for (int ph = 0; ph < 2; ++ph) {
        if ((warp_m >> 1) == ph) {
#pragma unroll
            for (int i = 0; i < FM; ++i)
#pragma unroll
                for (int j = 0; j < FN; ++j)
                    wmma::store_matrix_sync(
                        Cs + ((warp_m & 1) * 32 + i * 16) * BNP + warp_n * WN + j * 16,
                        acc[i][j], BNP, wmma::mem_row_major);
        }
        __syncthreads();
#pragma unroll
        for (int i = tid; i < 64 * BN / 4; i += 256) {
            const int row  = i / (BN / 4);
            const int cc   = (i % (BN / 4)) * 4;
            const int grow = m0 + ph * 64 + row;
            if (grow < M) {
                float4 v = *reinterpret_cast<const float4*>(Cs + row * BNP + cc);
                const float4 bb = *reinterpret_cast<const float4*>(bias + cc);
                if (FUSED) {
                    const float swv  = sw[grow];
                    const float invd = 1.f / fmaxf(deg[grow], 1.f);
                    const float4 pp  = *reinterpret_cast<const float4*>(P + (size_t)grow * BN + cc);
                    v.x = 0.5f * (fmaxf((v.x + swv * bb.x) * invd, 0.f) + pp.x);
                    v.y = 0.5f * (fmaxf((v.y + swv * bb.y) * invd, 0.f) + pp.y);
                    v.z = 0.5f * (fmaxf((v.z + swv * bb.z) * invd, 0.f) + pp.z);
                    v.w = 0.5f * (fmaxf((v.w + swv * bb.w) * invd, 0.f) + pp.w);
                } else {
                    v.x += bb.x; v.y += bb.y; v.z += bb.z; v.w += bb.w;
                }
                *reinterpret_cast<float4*>(C + (size_t)grow * BN + cc) = v;
            }
        }
        __syncthreads();
    }
}

// ---------------------------------------------------------------------------
// Host side
// ---------------------------------------------------------------------------
extern "C" void kernel_launch(void* const* d_in, const int* in_sizes, int n_in,
                              void* d_out, int out_size)
{
    const float* feat = (const float*)d_in[0];
    const int* src0[2] = {(const int*)d_in[1], (const int*)d_in[3]};
    const int* dst0[2] = {(const int*)d_in[2], (const int*)d_in[4]};
    const int* src1[2] = {(const int*)d_in[5], (const int*)d_in[7]};
    const int* dst1[2] = {(const int*)d_in[6], (const int*)d_in[8]};
    const int E0 = in_sizes[1];
    const int E1 = in_sizes[5];

    const int b = n_in - 14;
    const float* Win  = (const float*)d_in[b + 0];
    const float* b_in = (const float*)d_in[b + 1];
    const float* na1  = (const float*)d_in[b + 2];
    const float* ea1  = (const float*)d_in[b + 3];
    const float* ia1  = (const float*)d_in[b + 4];
    const float* W1   = (const float*)d_in[b + 5];
    const float* b1   = (const float*)d_in[b + 6];
    const float* na2  = (const float*)d_in[b + 7];
    const float* ea2  = (const float*)d_in[b + 8];
    const float* ia2  = (const float*)d_in[b + 9];
    const float* W2   = (const float*)d_in[b + 10];
    const float* b2   = (const float*)d_in[b + 11];
    const float* Wout = (const float*)d_in[b + 12];
    const float* bout = (const float*)d_in[b + 13];

    const int F = in_sizes[b + 0] / (2 * D);  // 256
    const int n_src0 = in_sizes[0] / F;       // 100000
    const int n_dst0 = NDST0;
    const int n_dst1 = NDST1;
    const int n_src1 = n_dst0;

    float4 *z0, *z1, *z2, *sone, *P4;
    float *sw, *deg, *pi_src, *pi_dst;
    float2 *pe_src, *pe_dst, *nalpha;
    int *cnt, *cur, *row[4], *col[4];
    cudaGetSymbolAddress((void**)&z0, g_z0);
    cudaGetSymbolAddress((void**)&z1, g_z1);
    cudaGetSymbolAddress((void**)&z2, g_z2);
    cudaGetSymbolAddress((void**)&sone, g_sone);
    cudaGetSymbolAddress((void**)&P4, g_p);
    cudaGetSymbolAddress((void**)&sw, g_sw);
    cudaGetSymbolAddress((void**)&deg, g_deg);
    cudaGetSymbolAddress((void**)&pe_src, g_pe_src);
    cudaGetSymbolAddress((void**)&pe_dst, g_pe_dst);
    cudaGetSymbolAddress((void**)&pi_src, g_pi_src);
    cudaGetSymbolAddress((void**)&pi_dst, g_pi_dst);
    cudaGetSymbolAddress((void**)&nalpha, g_nalpha);
    cudaGetSymbolAddress((void**)&cnt, g_cnt);
    cudaGetSymbolAddress((void**)&cur, g_cur);
    cudaGetSymbolAddress((void**)&row[0], g_row0);
    cudaGetSymbolAddress((void**)&row[1], g_row1);
    cudaGetSymbolAddress((void**)&row[2], g_row2);
    cudaGetSymbolAddress((void**)&row[3], g_row3);
    cudaGetSymbolAddress((void**)&col[0], g_col0);
    cudaGetSymbolAddress((void**)&col[1], g_col1);
    cudaGetSymbolAddress((void**)&col[2], g_col2);
    cudaGetSymbolAddress((void**)&col[3], g_col3);

    // ---- Batched CSR build (4 lists, 4 launches total) ----
    const int Etot = 2 * E0 + 2 * E1;
    cudaMemsetAsync(cnt, 0, sizeof(int) * (2 * NDST0 + 2 * NDST1));
    hist4_kernel<<<(Etot + 255) / 256, 256>>>(dst0[0], dst0[1], dst1[0], dst1[1], E0, E1, cnt);
    scan4_kernel<<<4, 1024>>>(cnt, cur, row[0], row[1], row[2], row[3]);
    fill4_kernel<<<(Etot + 255) / 256, 256>>>(src0[0], dst0[0], src0[1], dst0[1],
                                              src1[0], dst1[0], src1[1], dst1[1],
                                              E0, E1, cur, col[0], col[1], col[2], col[3]);

    float* out = (float*)d_out;

    for (int m = 0; m < 2; ++m) {
        // z0 = feat @ Win[m] + b_in[m]
        gemm_pipe_kernel<128, false><<<(n_src0 + 127) / 128, 256>>>(
            feat, Win + (size_t)m * F * D, b_in + (size_t)m * D,
            (float*)z0, n_src0, F, nullptr, nullptr, nullptr);

        // ---- Layer 1 on graph 0 ----
        proj_kernel<<<(n_src0 * 32 + 255) / 256, 256>>>(
            z0, n_src0, n_dst0,
            na1 + (size_t)m * D * 2, ea1 + (size_t)m * 2 * D * 2, ia1 + (size_t)m * 2 * D,
            pe_src, pe_dst, pi_src, pi_dst, nalpha);

        agg_kernel<<<(n_dst0 * 32 + 255) / 256, 256>>>(
            n_dst0, row[m], col[m], row[1 - m], col[1 - m],
            pe_src, pe_dst, pi_src, pi_dst, nalpha, z0,
            sone, P4, sw, deg);

        gemm_pipe_kernel<128, true><<<(n_dst0 + 127) / 128, 256>>>(
            (const float*)sone, W1 + (size_t)m * D * D, b1 + (size_t)m * D,
            (float*)z1, n_dst0, D, (const float*)P4, sw, deg);

        // ---- Layer 2 on graph 1 ----
        proj_kernel<<<(n_src1 * 32 + 255) / 256, 256>>>(
            z1, n_src1, n_dst1,
            na2 + (size_t)m * D * 2, ea2 + (size_t)m * 2 * D * 2, ia2 + (size_t)m * 2 * D,
            pe_src, pe_dst, pi_src, pi_dst, nalpha);

        agg_kernel<<<(n_dst1 * 32 + 255) / 256, 256>>>(
            n_dst1, row[2 + m], col[2 + m], row[2 + (1 - m)], col[2 + (1 - m)],
            pe_src, pe_dst, pi_src, pi_dst, nalpha, z1,
            sone, P4, sw, deg);

        gemm_pipe_kernel<128, true><<<(n_dst1 + 127) / 128, 256>>>(
            (const float*)sone, W2 + (size_t)m * D * D, b2 + (size_t)m * D,
            (float*)z2, n_dst1, D, (const float*)P4, sw, deg);

        // out[m] = z2 @ Wout[m] + bout[m]
        gemm_pipe_kernel<64, false><<<(n_dst1 + 127) / 128, 256>>>(
            (const float*)z2, Wout + (size_t)m * D * OUTD, bout + (size_t)m * OUTD,
            out + (size_t)m * n_dst1 * OUTD, n_dst1, D, nullptr, nullptr, nullptr);
    }
    (void)out_size;
}